// round 2
// baseline (speedup 1.0000x reference)
#include <cuda_runtime.h>
#include <cuda_fp16.h>
#include <stdint.h>

#define NA   128   // atoms per graph
#define FIN  7     // input features
#define HID  64
#define OUTF 32

// padded smem strides (in __half elements) -> conflict-free fragment loads
#define AS_STRIDE  136
#define XT_STRIDE  136
#define HS_STRIDE  72
#define W2T_STRIDE 72
#define ZT_STRIDE  136

struct Smem {
    __half As[NA * AS_STRIDE];        // A, fp16, row-major [n][m]
    __half Xt[8 * XT_STRIDE];         // X^T, fp16, [f][m], f padded to 8 (col 7 = 0)
    __half Hs[NA * HS_STRIDE];        // h1, fp16, row-major [m][h]
    __half W2t[OUTF * W2T_STRIDE];    // W2^T, fp16, [o][h]
    __half Zt[OUTF * ZT_STRIDE];      // Z^T = (h1@W2)^T, fp16, [o][m]
    float  AXs[NA * 8];               // A@X, fp32, row-major [n][f(pad 8)]
    float  W1s[FIN * HID];
    float  b1s[HID];
    float  b2s[OUTF];
    float  W3s[32 * 32];
    float  b3s[32];
    float  W4s[32 * 16];
    float  b4s[16];
    float  W5s[16];
    float  b5s;
    float  pool[OUTF];                // column sums of relu(A@Z + b2)
};

__device__ __forceinline__ uint32_t ldh2(const __half* p) {
    return *reinterpret_cast<const uint32_t*>(p);
}

__device__ __forceinline__ void mma16816(float c[4], const uint32_t a[4], const uint32_t b[2]) {
    asm volatile(
        "mma.sync.aligned.m16n8k16.row.col.f32.f16.f16.f32 "
        "{%0,%1,%2,%3}, {%4,%5,%6,%7}, {%8,%9}, {%0,%1,%2,%3};\n"
        : "+f"(c[0]), "+f"(c[1]), "+f"(c[2]), "+f"(c[3])
        : "r"(a[0]), "r"(a[1]), "r"(a[2]), "r"(a[3]), "r"(b[0]), "r"(b[1]));
}

__global__ __launch_bounds__(256, 2)
void gcn_fused_kernel(const float* __restrict__ X, const float* __restrict__ A,
                      const float* __restrict__ W1, const float* __restrict__ b1,
                      const float* __restrict__ W2, const float* __restrict__ b2,
                      const float* __restrict__ W3, const float* __restrict__ b3,
                      const float* __restrict__ W4, const float* __restrict__ b4,
                      const float* __restrict__ W5, const float* __restrict__ b5,
                      float* __restrict__ out)
{
    extern __shared__ char smem_raw[];
    Smem& s = *reinterpret_cast<Smem*>(smem_raw);

    const int bidx = blockIdx.x;
    const int tid  = threadIdx.x;
    const int warp = tid >> 5;
    const int lane = tid & 31;
    const int g    = lane >> 2;   // group id 0..7 (row within tile)
    const int tg   = lane & 3;    // thread-in-group 0..3
    const int row0 = warp * 16;   // each warp owns 16 M-rows

    // ---------------- Stage: load + convert ----------------
    {
        const float4* Ab = reinterpret_cast<const float4*>(A + (size_t)bidx * NA * NA);
        #pragma unroll
        for (int i = tid; i < NA * NA / 4; i += 256) {
            float4 v = Ab[i];
            int row = i >> 5;            // 32 float4 per 128-wide row
            int c0  = (i & 31) << 2;
            __half2* dst = reinterpret_cast<__half2*>(&s.As[row * AS_STRIDE + c0]);
            dst[0] = __floats2half2_rn(v.x, v.y);
            dst[1] = __floats2half2_rn(v.z, v.w);
        }
        const float* Xb = X + (size_t)bidx * NA * FIN;
        for (int i = tid; i < NA * FIN; i += 256) {
            int m = i / FIN, f = i % FIN;
            s.Xt[f * XT_STRIDE + m] = __float2half(Xb[i]);
        }
        if (tid < NA) s.Xt[7 * XT_STRIDE + tid] = __float2half(0.f);  // zero pad col
        for (int i = tid; i < FIN * HID; i += 256) s.W1s[i] = W1[i];
        if (tid < HID) s.b1s[tid] = b1[tid];
        for (int i = tid; i < HID * OUTF; i += 256) {
            int k = i >> 5, n = i & 31;
            s.W2t[n * W2T_STRIDE + k] = __float2half(W2[i]);
        }
        if (tid < OUTF) s.b2s[tid] = b2[tid];
        for (int i = tid; i < 32 * 32; i += 256) s.W3s[i] = W3[i];
        if (tid < 32) s.b3s[tid] = b3[tid];
        for (int i = tid; i < 32 * 16; i += 256) s.W4s[i] = W4[i];
        if (tid < 16) s.b4s[tid] = b4[tid];
        if (tid < 16) s.W5s[tid] = W5[tid];
        if (tid == 0) s.b5s = b5[0];
        if (tid < OUTF) s.pool[tid] = 0.f;
    }
    __syncthreads();

    // ---------------- GEMM1: AX = A @ Xpad   (M=128, N=8, K=128) ----------------
    {
        float c[4] = {0.f, 0.f, 0.f, 0.f};
        #pragma unroll
        for (int k = 0; k < 128; k += 16) {
            uint32_t a[4], bb[2];
            const __half* ap = &s.As[(row0 + g) * AS_STRIDE + k + 2 * tg];
            a[0] = ldh2(ap);
            a[1] = ldh2(ap + 8 * AS_STRIDE);
            a[2] = ldh2(ap + 8);
            a[3] = ldh2(ap + 8 * AS_STRIDE + 8);
            const __half* bp = &s.Xt[g * XT_STRIDE + k + 2 * tg];
            bb[0] = ldh2(bp);
            bb[1] = ldh2(bp + 8);
            mma16816(c, a, bb);
        }
        s.AXs[(row0 + g)     * 8 + 2 * tg    ] = c[0];
        s.AXs[(row0 + g)     * 8 + 2 * tg + 1] = c[1];
        s.AXs[(row0 + g + 8) * 8 + 2 * tg    ] = c[2];
        s.AXs[(row0 + g + 8) * 8 + 2 * tg + 1] = c[3];
    }
    __syncthreads();

    // ---------------- h1 = relu(AX @ W1 + b1)  (FFMA, K=7) ----------------
    {
        int r  = tid & 127;
        int ch = (tid >> 7) * 32;   // this thread does 32 of the 64 hidden cols
        float ax[FIN];
        #pragma unroll
        for (int f = 0; f < FIN; f++) ax[f] = s.AXs[r * 8 + f];
        #pragma unroll 8
        for (int j = 0; j < 32; j++) {
            int col = ch + j;
            float acc = s.b1s[col];
            #pragma unroll
            for (int f = 0; f < FIN; f++)
                acc = fmaf(ax[f], s.W1s[f * HID + col], acc);
            s.Hs[r * HS_STRIDE + col] = __float2half(fmaxf(acc, 0.f));
        }
    }
    __syncthreads();

    // ---------------- GEMM2: Z = h1 @ W2  (M=128, N=32, K=64) ----------------
    {
        float c[4][4];
        #pragma unroll
        for (int nt = 0; nt < 4; nt++)
            #pragma unroll
            for (int r = 0; r < 4; r++) c[nt][r] = 0.f;
        #pragma unroll
        for (int k = 0; k < 64; k += 16) {
            uint32_t a[4];
            const __half* ap = &s.Hs[(row0 + g) * HS_STRIDE + k + 2 * tg];
            a[0] = ldh2(ap);
            a[1] = ldh2(ap + 8 * HS_STRIDE);
            a[2] = ldh2(ap + 8);
            a[3] = ldh2(ap + 8 * HS_STRIDE + 8);
            #pragma unroll
            for (int nt = 0; nt < 4; nt++) {
                uint32_t bb[2];
                const __half* bp = &s.W2t[(nt * 8 + g) * W2T_STRIDE + k + 2 * tg];
                bb[0] = ldh2(bp);
                bb[1] = ldh2(bp + 8);
                mma16816(c[nt], a, bb);
            }
        }
        #pragma unroll
        for (int nt = 0; nt < 4; nt++) {
            int ncol = nt * 8 + 2 * tg;
            s.Zt[ ncol      * ZT_STRIDE + row0 + g    ] = __float2half(c[nt][0]);
            s.Zt[(ncol + 1) * ZT_STRIDE + row0 + g    ] = __float2half(c[nt][1]);
            s.Zt[ ncol      * ZT_STRIDE + row0 + g + 8] = __float2half(c[nt][2]);
            s.Zt[(ncol + 1) * ZT_STRIDE + row0 + g + 8] = __float2half(c[nt][3]);
        }
    }
    __syncthreads();

    // ---------------- GEMM3: AZ = A @ Z (M=128, N=32, K=128) + bias/relu/pool ----------------
    {
        float c[4][4];
        #pragma unroll
        for (int nt = 0; nt < 4; nt++)
            #pragma unroll
            for (int r = 0; r < 4; r++) c[nt][r] = 0.f;
        #pragma unroll
        for (int k = 0; k < 128; k += 16) {
            uint32_t a[4];
            const __half* ap = &s.As[(row0 + g) * AS_STRIDE + k + 2 * tg];
            a[0] = ldh2(ap);
            a[1] = ldh2(ap + 8 * AS_STRIDE);
            a[2] = ldh2(ap + 8);
            a[3] = ldh2(ap + 8 * AS_STRIDE + 8);
            #pragma unroll
            for (int nt = 0; nt < 4; nt++) {
                uint32_t bb[2];
                const __half* bp = &s.Zt[(nt * 8 + g) * ZT_STRIDE + k + 2 * tg];
                bb[0] = ldh2(bp);
                bb[1] = ldh2(bp + 8);
                mma16816(c[nt], a, bb);
            }
        }
        // h2 = relu(AZ + b2); column-sum over the 128 rows (mean pool * 128)
        #pragma unroll
        for (int nt = 0; nt < 4; nt++) {
            int col = nt * 8 + 2 * tg;
            float bc0 = s.b2s[col], bc1 = s.b2s[col + 1];
            float s0 = fmaxf(c[nt][0] + bc0, 0.f) + fmaxf(c[nt][2] + bc0, 0.f);
            float s1 = fmaxf(c[nt][1] + bc1, 0.f) + fmaxf(c[nt][3] + bc1, 0.f);
            #pragma unroll
            for (int off = 16; off >= 4; off >>= 1) {
                s0 += __shfl_down_sync(0xffffffffu, s0, off);
                s1 += __shfl_down_sync(0xffffffffu, s1, off);
            }
            if (g == 0) {
                atomicAdd(&s.pool[col],     s0);
                atomicAdd(&s.pool[col + 1], s1);
            }
        }
    }
    __syncthreads();

    // ---------------- MLP head (fp32, warp 0) ----------------
    if (warp == 0) {
        float h = s.pool[lane] * (1.f / 128.f);   // mean over 128 atoms
        // layer 3: 32 -> 32
        float a3 = s.b3s[lane];
        #pragma unroll
        for (int i = 0; i < 32; i++)
            a3 = fmaf(__shfl_sync(0xffffffffu, h, i), s.W3s[i * 32 + lane], a3);
        a3 = fmaxf(a3, 0.f);
        // layer 4: 32 -> 16 (lanes >=16 compute duplicates, harmless)
        int l16 = lane & 15;
        float a4 = s.b4s[l16];
        #pragma unroll
        for (int i = 0; i < 32; i++)
            a4 = fmaf(__shfl_sync(0xffffffffu, a3, i), s.W4s[i * 16 + l16], a4);
        a4 = fmaxf(a4, 0.f);
        // layer 5: 16 -> 1
        float y = 0.f;
        #pragma unroll
        for (int i = 0; i < 16; i++)
            y = fmaf(__shfl_sync(0xffffffffu, a4, i), s.W5s[i], y);
        if (lane == 0) out[bidx] = y + s.b5s;
    }
}

extern "C" void kernel_launch(void* const* d_in, const int* in_sizes, int n_in,
                              void* d_out, int out_size)
{
    const float* X  = (const float*)d_in[0];
    const float* A  = (const float*)d_in[1];
    const float* W1 = (const float*)d_in[2];
    const float* b1 = (const float*)d_in[3];
    const float* W2 = (const float*)d_in[4];
    const float* b2 = (const float*)d_in[5];
    const float* W3 = (const float*)d_in[6];
    const float* b3 = (const float*)d_in[7];
    const float* W4 = (const float*)d_in[8];
    const float* b4 = (const float*)d_in[9];
    const float* W5 = (const float*)d_in[10];
    const float* b5 = (const float*)d_in[11];
    float* out = (float*)d_out;

    int batch = in_sizes[1] / (NA * NA);

    cudaFuncSetAttribute(gcn_fused_kernel,
                         cudaFuncAttributeMaxDynamicSharedMemorySize,
                         (int)sizeof(Smem));

    gcn_fused_kernel<<<batch, 256, sizeof(Smem)>>>(X, A, W1, b1, W2, b2,
                                                   W3, b3, W4, b4, W5, b5, out);
}

// round 3
// speedup vs baseline: 1.0628x; 1.0628x over previous
#include <cuda_runtime.h>
#include <cuda_fp16.h>
#include <stdint.h>

#define NA   128
#define FIN  7
#define HID  64
#define OUTF 32

// strides in __half elements (row stride = +4 banks mod 32 -> LDSM conflict-free)
#define AS_STRIDE  136
#define XT_STRIDE  136
#define HS_STRIDE  72
#define W2T_STRIDE 72
#define ZT_STRIDE  136

// ---- smem layout (bytes), with Zt union'd over {Xt, AXs, W1s, b1s} ----
#define AS_OFF    0
#define AS_BYTES  (NA * AS_STRIDE * 2)          // 34816
#define HS_OFF    (AS_OFF + AS_BYTES)
#define HS_BYTES  (NA * HS_STRIDE * 2)          // 18432
#define W2T_OFF   (HS_OFF + HS_BYTES)
#define W2T_BYTES (OUTF * W2T_STRIDE * 2)       // 4608
#define U_OFF     (W2T_OFF + W2T_BYTES)
#define XT_OFF    (U_OFF)                       // 8*136*2 = 2176
#define AXS_OFF   (U_OFF + 2176)                // 128*8*4 = 4096
#define W1S_OFF   (AXS_OFF + 4096)              // 7*64*4 = 1792
#define B1S_OFF   (W1S_OFF + 1792)              // 64*4   = 256
#define ZT_OFF    (U_OFF)                       // 32*136*2 = 8704 (overlaps the above)
#define U_BYTES   8704
#define B2S_OFF   (U_OFF + U_BYTES)             // 128
#define POOL_OFF  (B2S_OFF + 128)               // 128
#define SMEM_TOTAL (POOL_OFF + 128)             // 66816 bytes -> 3 CTAs/SM

__device__ __forceinline__ uint32_t sptr(const void* p) {
    return (uint32_t)__cvta_generic_to_shared(p);
}

__device__ __forceinline__ void ldsm_x4(uint32_t& r0, uint32_t& r1, uint32_t& r2, uint32_t& r3,
                                        uint32_t addr) {
    asm volatile("ldmatrix.sync.aligned.m8n8.x4.shared.b16 {%0,%1,%2,%3}, [%4];\n"
                 : "=r"(r0), "=r"(r1), "=r"(r2), "=r"(r3) : "r"(addr));
}

__device__ __forceinline__ void ldsm_x2(uint32_t& r0, uint32_t& r1, uint32_t addr) {
    asm volatile("ldmatrix.sync.aligned.m8n8.x2.shared.b16 {%0,%1}, [%2];\n"
                 : "=r"(r0), "=r"(r1) : "r"(addr));
}

__device__ __forceinline__ void mma16816(float c[4], const uint32_t a[4], const uint32_t b[2]) {
    asm volatile(
        "mma.sync.aligned.m16n8k16.row.col.f32.f16.f16.f32 "
        "{%0,%1,%2,%3}, {%4,%5,%6,%7}, {%8,%9}, {%0,%1,%2,%3};\n"
        : "+f"(c[0]), "+f"(c[1]), "+f"(c[2]), "+f"(c[3])
        : "r"(a[0]), "r"(a[1]), "r"(a[2]), "r"(a[3]), "r"(b[0]), "r"(b[1]));
}

__global__ __launch_bounds__(256, 3)
void gcn_fused_kernel(const float* __restrict__ X, const float* __restrict__ A,
                      const float* __restrict__ W1, const float* __restrict__ b1,
                      const float* __restrict__ W2, const float* __restrict__ b2,
                      const float* __restrict__ W3, const float* __restrict__ b3,
                      const float* __restrict__ W4, const float* __restrict__ b4,
                      const float* __restrict__ W5, const float* __restrict__ b5,
                      float* __restrict__ out)
{
    extern __shared__ char smem[];
    __half* As  = reinterpret_cast<__half*>(smem + AS_OFF);
    __half* Hs  = reinterpret_cast<__half*>(smem + HS_OFF);
    __half* W2t = reinterpret_cast<__half*>(smem + W2T_OFF);
    __half* Xt  = reinterpret_cast<__half*>(smem + XT_OFF);
    float*  AXs = reinterpret_cast<float*>(smem + AXS_OFF);
    float*  W1s = reinterpret_cast<float*>(smem + W1S_OFF);
    float*  b1s = reinterpret_cast<float*>(smem + B1S_OFF);
    __half* Zt  = reinterpret_cast<__half*>(smem + ZT_OFF);
    float*  b2s = reinterpret_cast<float*>(smem + B2S_OFF);
    float*  pool = reinterpret_cast<float*>(smem + POOL_OFF);

    const int bidx = blockIdx.x;
    const int tid  = threadIdx.x;
    const int warp = tid >> 5;
    const int lane = tid & 31;
    const int g    = lane >> 2;
    const int tg   = lane & 3;
    const int row0 = warp * 16;

    // ---------------- Stage ----------------
    {
        const float4* Ab = reinterpret_cast<const float4*>(A + (size_t)bidx * NA * NA);
        #pragma unroll
        for (int i = tid; i < NA * NA / 4; i += 256) {
            float4 v = Ab[i];
            int row = i >> 5;
            int c0  = (i & 31) << 2;
            __half2 h01 = __floats2half2_rn(v.x, v.y);
            __half2 h23 = __floats2half2_rn(v.z, v.w);
            *reinterpret_cast<uint2*>(&As[row * AS_STRIDE + c0]) =
                make_uint2(*reinterpret_cast<uint32_t*>(&h01),
                           *reinterpret_cast<uint32_t*>(&h23));
        }
        const float* Xb = X + (size_t)bidx * NA * FIN;
        for (int i = tid; i < NA * FIN; i += 256) {
            int m = i / FIN, f = i % FIN;
            Xt[f * XT_STRIDE + m] = __float2half(Xb[i]);
        }
        if (tid < NA) Xt[7 * XT_STRIDE + tid] = __float2half(0.f);
        for (int i = tid; i < FIN * HID; i += 256) W1s[i] = W1[i];
        if (tid < HID) b1s[tid] = b1[tid];
        for (int i = tid; i < HID * OUTF; i += 256) {
            int k = i >> 5, n = i & 31;
            W2t[n * W2T_STRIDE + k] = __float2half(W2[i]);
        }
        if (tid < OUTF) b2s[tid] = b2[tid];
        if (tid < OUTF) pool[tid] = 0.f;
    }
    __syncthreads();

    // ---------------- GEMM1: AX = A @ Xpad  (M=128, N=8, K=128) ----------------
    {
        float c[4] = {0.f, 0.f, 0.f, 0.f};
        uint32_t aAddr = sptr(&As[(row0 + (lane & 15)) * AS_STRIDE + ((lane >> 4) << 3)]);
        uint32_t bAddr = sptr(&Xt[(lane & 7) * XT_STRIDE + (((lane >> 3) & 1) << 3)]);
        #pragma unroll
        for (int k = 0; k < 128; k += 16) {
            uint32_t a[4], bb[2];
            ldsm_x4(a[0], a[1], a[2], a[3], aAddr + 2 * k);
            ldsm_x2(bb[0], bb[1], bAddr + 2 * k);
            mma16816(c, a, bb);
        }
        AXs[(row0 + g)     * 8 + 2 * tg    ] = c[0];
        AXs[(row0 + g)     * 8 + 2 * tg + 1] = c[1];
        AXs[(row0 + g + 8) * 8 + 2 * tg    ] = c[2];
        AXs[(row0 + g + 8) * 8 + 2 * tg + 1] = c[3];
    }
    __syncthreads();

    // ---------------- h1 = relu(AX @ W1 + b1)  (FFMA, K=7) ----------------
    {
        int r  = tid & 127;
        int ch = (tid >> 7) * 32;
        float ax[FIN];
        #pragma unroll
        for (int f = 0; f < FIN; f++) ax[f] = AXs[r * 8 + f];
        #pragma unroll 4
        for (int j = 0; j < 32; j += 2) {
            int col = ch + j;
            float acc0 = b1s[col], acc1 = b1s[col + 1];
            #pragma unroll
            for (int f = 0; f < FIN; f++) {
                acc0 = fmaf(ax[f], W1s[f * HID + col],     acc0);
                acc1 = fmaf(ax[f], W1s[f * HID + col + 1], acc1);
            }
            *reinterpret_cast<__half2*>(&Hs[r * HS_STRIDE + col]) =
                __floats2half2_rn(fmaxf(acc0, 0.f), fmaxf(acc1, 0.f));
        }
    }
    __syncthreads();

    // ---------------- GEMM2: Z = h1 @ W2  (M=128, N=32, K=64) ----------------
    {
        float c[4][4];
        #pragma unroll
        for (int nt = 0; nt < 4; nt++)
            #pragma unroll
            for (int r = 0; r < 4; r++) c[nt][r] = 0.f;
        uint32_t aAddr = sptr(&Hs[(row0 + (lane & 15)) * HS_STRIDE + ((lane >> 4) << 3)]);
        // B addr: lane -> n = 8*(lane>>4) + (lane&7), k-offset = 8*((lane>>3)&1)
        uint32_t bAddr = sptr(&W2t[(((lane >> 4) << 3) + (lane & 7)) * W2T_STRIDE +
                                   (((lane >> 3) & 1) << 3)]);
        const uint32_t bStep = 16 * W2T_STRIDE * 2;  // +16 n-rows in bytes
        #pragma unroll
        for (int k = 0; k < 64; k += 16) {
            uint32_t a[4], bb[8];
            ldsm_x4(a[0], a[1], a[2], a[3], aAddr + 2 * k);
            ldsm_x4(bb[0], bb[1], bb[2], bb[3], bAddr + 2 * k);          // ntiles 0,1
            ldsm_x4(bb[4], bb[5], bb[6], bb[7], bAddr + bStep + 2 * k);  // ntiles 2,3
            mma16816(c[0], a, bb + 0);
            mma16816(c[1], a, bb + 2);
            mma16816(c[2], a, bb + 4);
            mma16816(c[3], a, bb + 6);
        }
        // NOTE: Zt overlaps the {Xt,AXs,W1s,b1s} region; all reads of those finished
        // before the preceding __syncthreads().
        #pragma unroll
        for (int nt = 0; nt < 4; nt++) {
            int ncol = nt * 8 + 2 * tg;
            Zt[ ncol      * ZT_STRIDE + row0 + g    ] = __float2half(c[nt][0]);
            Zt[(ncol + 1) * ZT_STRIDE + row0 + g    ] = __float2half(c[nt][1]);
            Zt[ ncol      * ZT_STRIDE + row0 + g + 8] = __float2half(c[nt][2]);
            Zt[(ncol + 1) * ZT_STRIDE + row0 + g + 8] = __float2half(c[nt][3]);
        }
    }
    __syncthreads();

    // ---------------- GEMM3: AZ = A @ Z (M=128, N=32, K=128) + bias/relu/pool ----------------
    {
        float c[4][4];
        #pragma unroll
        for (int nt = 0; nt < 4; nt++)
            #pragma unroll
            for (int r = 0; r < 4; r++) c[nt][r] = 0.f;
        uint32_t aAddr = sptr(&As[(row0 + (lane & 15)) * AS_STRIDE + ((lane >> 4) << 3)]);
        uint32_t bAddr = sptr(&Zt[(((lane >> 4) << 3) + (lane & 7)) * ZT_STRIDE +
                                  (((lane >> 3) & 1) << 3)]);
        const uint32_t bStep = 16 * ZT_STRIDE * 2;
        #pragma unroll
        for (int k = 0; k < 128; k += 16) {
            uint32_t a[4], bb[8];
            ldsm_x4(a[0], a[1], a[2], a[3], aAddr + 2 * k);
            ldsm_x4(bb[0], bb[1], bb[2], bb[3], bAddr + 2 * k);
            ldsm_x4(bb[4], bb[5], bb[6], bb[7], bAddr + bStep + 2 * k);
            mma16816(c[0], a, bb + 0);
            mma16816(c[1], a, bb + 2);
            mma16816(c[2], a, bb + 4);
            mma16816(c[3], a, bb + 6);
        }
        #pragma unroll
        for (int nt = 0; nt < 4; nt++) {
            int col = nt * 8 + 2 * tg;
            float bc0 = b2s[col], bc1 = b2s[col + 1];
            float s0 = fmaxf(c[nt][0] + bc0, 0.f) + fmaxf(c[nt][2] + bc0, 0.f);
            float s1 = fmaxf(c[nt][1] + bc1, 0.f) + fmaxf(c[nt][3] + bc1, 0.f);
            #pragma unroll
            for (int off = 16; off >= 4; off >>= 1) {
                s0 += __shfl_down_sync(0xffffffffu, s0, off);
                s1 += __shfl_down_sync(0xffffffffu, s1, off);
            }
            if (g == 0) {
                atomicAdd(&pool[col],     s0);
                atomicAdd(&pool[col + 1], s1);
            }
        }
    }
    __syncthreads();

    // ---------------- MLP head (fp32, warp 0; weights straight from L2-hot gmem) ----------------
    if (warp == 0) {
        float h = pool[lane] * (1.f / 128.f);
        float a3 = b3[lane];
        #pragma unroll
        for (int i = 0; i < 32; i++)
            a3 = fmaf(__shfl_sync(0xffffffffu, h, i), W3[i * 32 + lane], a3);
        a3 = fmaxf(a3, 0.f);
        int l16 = lane & 15;
        float a4 = b4[l16];
        #pragma unroll
        for (int i = 0; i < 32; i++)
            a4 = fmaf(__shfl_sync(0xffffffffu, a3, i), W4[i * 16 + l16], a4);
        a4 = fmaxf(a4, 0.f);
        float y = 0.f;
        #pragma unroll
        for (int i = 0; i < 16; i++)
            y = fmaf(__shfl_sync(0xffffffffu, a4, i), W5[i], y);
        if (lane == 0) out[bidx] = y + b5[0];
    }
}

extern "C" void kernel_launch(void* const* d_in, const int* in_sizes, int n_in,
                              void* d_out, int out_size)
{
    const float* X  = (const float*)d_in[0];
    const float* A  = (const float*)d_in[1];
    const float* W1 = (const float*)d_in[2];
    const float* b1 = (const float*)d_in[3];
    const float* W2 = (const float*)d_in[4];
    const float* b2 = (const float*)d_in[5];
    const float* W3 = (const float*)d_in[6];
    const float* b3 = (const float*)d_in[7];
    const float* W4 = (const float*)d_in[8];
    const float* b4 = (const float*)d_in[9];
    const float* W5 = (const float*)d_in[10];
    const float* b5 = (const float*)d_in[11];
    float* out = (float*)d_out;

    int batch = in_sizes[1] / (NA * NA);

    cudaFuncSetAttribute(gcn_fused_kernel,
                         cudaFuncAttributeMaxDynamicSharedMemorySize, SMEM_TOTAL);

    gcn_fused_kernel<<<batch, 256, SMEM_TOTAL>>>(X, A, W1, b1, W2, b2,
                                                 W3, b3, W4, b4, W5, b5, out);
}

// round 5
// speedup vs baseline: 1.5460x; 1.4547x over previous
#include <cuda_runtime.h>
#include <cuda_fp16.h>
#include <stdint.h>

#define NA   128
#define FIN  7
#define HID  64
#define OUTF 32

#define AS_STRIDE  136
#define XT_STRIDE  136
#define HS_STRIDE  72
#define W2T_STRIDE 72
#define ZT_STRIDE  136

// ---- smem layout (bytes) ----
#define AS_OFF     0
#define AS_BYTES   (NA * AS_STRIDE * 2)        // 34816
#define HS_OFF     (AS_OFF + AS_BYTES)
#define HS_BYTES   (NA * HS_STRIDE * 2)        // 18432
#define W2T_OFF    (HS_OFF + HS_BYTES)
#define W2T_BYTES  (OUTF * W2T_STRIDE * 2)     // 4608
#define W1S_OFF    (W2T_OFF + W2T_BYTES)       // 1792
#define B1S_OFF    (W1S_OFF + 1792)            // 256
#define B2S_OFF    (B1S_OFF + 256)             // 128
#define U_OFF      (B2S_OFF + 128)
#define XT_OFF     (U_OFF)                     // 8*136*2 = 2176
#define AXS_OFF    (U_OFF + 2176)              // 128*8*4 = 4096
#define ZT_OFF     (U_OFF)                     // 32*136*2 = 8704 (overlaps Xt/AXs)
#define U_BYTES    8704
#define POOL2_OFF  (U_OFF + U_BYTES)           // 8*32*4 = 1024
#define SMEM_TOTAL (POOL2_OFF + 1024)          // 69760 -> 3 CTAs/SM

__device__ __forceinline__ uint32_t sptr(const void* p) {
    return (uint32_t)__cvta_generic_to_shared(p);
}
__device__ __forceinline__ void ldsm_x4(uint32_t& r0, uint32_t& r1, uint32_t& r2, uint32_t& r3,
                                        uint32_t addr) {
    asm volatile("ldmatrix.sync.aligned.m8n8.x4.shared.b16 {%0,%1,%2,%3}, [%4];\n"
                 : "=r"(r0), "=r"(r1), "=r"(r2), "=r"(r3) : "r"(addr));
}
__device__ __forceinline__ void ldsm_x2(uint32_t& r0, uint32_t& r1, uint32_t addr) {
    asm volatile("ldmatrix.sync.aligned.m8n8.x2.shared.b16 {%0,%1}, [%2];\n"
                 : "=r"(r0), "=r"(r1) : "r"(addr));
}
__device__ __forceinline__ void mma16816(float c[4], const uint32_t a[4], const uint32_t b[2]) {
    asm volatile(
        "mma.sync.aligned.m16n8k16.row.col.f32.f16.f16.f32 "
        "{%0,%1,%2,%3}, {%4,%5,%6,%7}, {%8,%9}, {%0,%1,%2,%3};\n"
        : "+f"(c[0]), "+f"(c[1]), "+f"(c[2]), "+f"(c[3])
        : "r"(a[0]), "r"(a[1]), "r"(a[2]), "r"(a[3]), "r"(b[0]), "r"(b[1]));
}
__device__ __forceinline__ void prefetchL2(const void* p) {
    asm volatile("prefetch.global.L2 [%0];" :: "l"(p));
}

__global__ __launch_bounds__(256, 3)
void gcn_fused_kernel(const float* __restrict__ X, const float* __restrict__ A,
                      const float* __restrict__ W1, const float* __restrict__ b1,
                      const float* __restrict__ W2, const float* __restrict__ b2,
                      const float* __restrict__ W3, const float* __restrict__ b3,
                      const float* __restrict__ W4, const float* __restrict__ b4,
                      const float* __restrict__ W5, const float* __restrict__ b5,
                      float* __restrict__ out, int batch)
{
    extern __shared__ char smem[];
    __half* As   = reinterpret_cast<__half*>(smem + AS_OFF);
    __half* Hs   = reinterpret_cast<__half*>(smem + HS_OFF);
    __half* W2t  = reinterpret_cast<__half*>(smem + W2T_OFF);
    float*  W1s  = reinterpret_cast<float*>(smem + W1S_OFF);
    float*  b1s  = reinterpret_cast<float*>(smem + B1S_OFF);
    float*  b2s  = reinterpret_cast<float*>(smem + B2S_OFF);
    __half* Xt   = reinterpret_cast<__half*>(smem + XT_OFF);
    float*  AXs  = reinterpret_cast<float*>(smem + AXS_OFF);
    __half* Zt   = reinterpret_cast<__half*>(smem + ZT_OFF);
    float*  pool2 = reinterpret_cast<float*>(smem + POOL2_OFF);

    const int tid  = threadIdx.x;
    const int warp = tid >> 5;
    const int lane = tid & 31;
    const int g    = lane >> 2;
    const int tg   = lane & 3;
    const int row0 = warp * 16;

    // ---------- stage persistent weights ONCE ----------
    for (int i = tid; i < FIN * HID; i += 256) W1s[i] = W1[i];
    if (tid < HID)  b1s[tid] = b1[tid];
    for (int i = tid; i < HID * OUTF; i += 256) {
        int k = i >> 5, n = i & 31;
        W2t[n * W2T_STRIDE + k] = __float2half(W2[i]);
    }
    if (tid < OUTF) b2s[tid] = b2[tid];
    __syncthreads();

    #pragma unroll 1
    for (int gr = blockIdx.x; gr < batch; gr += gridDim.x) {
        const float* Ab = A + (size_t)gr * NA * NA;
        const float* Xb = X + (size_t)gr * NA * FIN;

        // ---------- stage A + X (warp-local: each warp owns 16 rows) ----------
        {
            const float4* Ab4 = reinterpret_cast<const float4*>(Ab);
            #pragma unroll
            for (int i = lane; i < 512; i += 32) {
                float4 v = Ab4[warp * 512 + i];
                int row = row0 + (i >> 5);
                int c0  = (i & 31) << 2;
                __half2 h01 = __floats2half2_rn(v.x, v.y);
                __half2 h23 = __floats2half2_rn(v.z, v.w);
                *reinterpret_cast<uint2*>(&As[row * AS_STRIDE + c0]) =
                    make_uint2(*reinterpret_cast<uint32_t*>(&h01),
                               *reinterpret_cast<uint32_t*>(&h23));
            }
            #pragma unroll
            for (int i = lane; i < 16 * FIN; i += 32) {
                int m = row0 + i / FIN, f = i % FIN;
                Xt[f * XT_STRIDE + m] = __float2half(Xb[m * FIN + f]);
            }
            if (lane < 16) Xt[7 * XT_STRIDE + row0 + lane] = __half(0.f);
        }

        // ---------- prefetch NEXT graph's A/X into L2 (overlaps all compute) ----------
        {
            int gn = gr + gridDim.x;
            if (gn < batch) {
                const char* An = reinterpret_cast<const char*>(A + (size_t)gn * NA * NA);
                prefetchL2(An + tid * 128);
                prefetchL2(An + (tid + 256) * 128);
                const char* Xn = reinterpret_cast<const char*>(X + (size_t)gn * NA * FIN);
                if (tid < 28) prefetchL2(Xn + tid * 128);
            }
        }
        __syncthreads();

        // ---------- GEMM1: AX = A @ Xpad (M=128, N=8, K=128) ----------
        {
            float c[4] = {0.f, 0.f, 0.f, 0.f};
            uint32_t aAddr = sptr(&As[(row0 + (lane & 15)) * AS_STRIDE + ((lane >> 4) << 3)]);
            uint32_t bAddr = sptr(&Xt[(lane & 7) * XT_STRIDE + (((lane >> 3) & 1) << 3)]);
            #pragma unroll
            for (int k = 0; k < 128; k += 16) {
                uint32_t a[4], bb[2];
                ldsm_x4(a[0], a[1], a[2], a[3], aAddr + 2 * k);
                ldsm_x2(bb[0], bb[1], bAddr + 2 * k);
                mma16816(c, a, bb);
            }
            AXs[(row0 + g)     * 8 + 2 * tg    ] = c[0];
            AXs[(row0 + g)     * 8 + 2 * tg + 1] = c[1];
            AXs[(row0 + g + 8) * 8 + 2 * tg    ] = c[2];
            AXs[(row0 + g + 8) * 8 + 2 * tg + 1] = c[3];
        }
        __syncthreads();

        // ---------- h1 = relu(AX @ W1 + b1) ----------
        {
            int r  = tid & 127;
            int ch = (tid >> 7) * 32;
            float ax[FIN];
            #pragma unroll
            for (int f = 0; f < FIN; f++) ax[f] = AXs[r * 8 + f];
            #pragma unroll 4
            for (int j = 0; j < 32; j += 2) {
                int col = ch + j;
                float acc0 = b1s[col], acc1 = b1s[col + 1];
                #pragma unroll
                for (int f = 0; f < FIN; f++) {
                    acc0 = fmaf(ax[f], W1s[f * HID + col],     acc0);
                    acc1 = fmaf(ax[f], W1s[f * HID + col + 1], acc1);
                }
                *reinterpret_cast<__half2*>(&Hs[r * HS_STRIDE + col]) =
                    __floats2half2_rn(fmaxf(acc0, 0.f), fmaxf(acc1, 0.f));
            }
        }
        __syncthreads();

        // ---------- GEMM2: Z = h1 @ W2 (M=128, N=32, K=64) ----------
        {
            float c[4][4];
            #pragma unroll
            for (int nt = 0; nt < 4; nt++)
                #pragma unroll
                for (int r = 0; r < 4; r++) c[nt][r] = 0.f;
            uint32_t aAddr = sptr(&Hs[(row0 + (lane & 15)) * HS_STRIDE + ((lane >> 4) << 3)]);
            uint32_t bAddr = sptr(&W2t[(((lane >> 4) << 3) + (lane & 7)) * W2T_STRIDE +
                                       (((lane >> 3) & 1) << 3)]);
            const uint32_t bStep = 16 * W2T_STRIDE * 2;
            #pragma unroll
            for (int k = 0; k < 64; k += 16) {
                uint32_t a[4], bb[8];
                ldsm_x4(a[0], a[1], a[2], a[3], aAddr + 2 * k);
                ldsm_x4(bb[0], bb[1], bb[2], bb[3], bAddr + 2 * k);
                ldsm_x4(bb[4], bb[5], bb[6], bb[7], bAddr + bStep + 2 * k);
                mma16816(c[0], a, bb + 0);
                mma16816(c[1], a, bb + 2);
                mma16816(c[2], a, bb + 4);
                mma16816(c[3], a, bb + 6);
            }
            __syncthreads();   // Zt overlaps Xt/AXs: wait for all h1/G1 readers
            #pragma unroll
            for (int nt = 0; nt < 4; nt++) {
                int ncol = nt * 8 + 2 * tg;
                Zt[ ncol      * ZT_STRIDE + row0 + g    ] = __float2half(c[nt][0]);
                Zt[(ncol + 1) * ZT_STRIDE + row0 + g    ] = __float2half(c[nt][1]);
                Zt[ ncol      * ZT_STRIDE + row0 + g + 8] = __float2half(c[nt][2]);
                Zt[(ncol + 1) * ZT_STRIDE + row0 + g + 8] = __float2half(c[nt][3]);
            }
        }
        __syncthreads();

        // ---------- GEMM3: AZ = A @ Z (M=128, N=32, K=128) + bias/relu/pool ----------
        {
            float c[4][4];
            #pragma unroll
            for (int nt = 0; nt < 4; nt++)
                #pragma unroll
                for (int r = 0; r < 4; r++) c[nt][r] = 0.f;
            uint32_t aAddr = sptr(&As[(row0 + (lane & 15)) * AS_STRIDE + ((lane >> 4) << 3)]);
            uint32_t bAddr = sptr(&Zt[(((lane >> 4) << 3) + (lane & 7)) * ZT_STRIDE +
                                      (((lane >> 3) & 1) << 3)]);
            const uint32_t bStep = 16 * ZT_STRIDE * 2;
            #pragma unroll
            for (int k = 0; k < 128; k += 16) {
                uint32_t a[4], bb[8];
                ldsm_x4(a[0], a[1], a[2], a[3], aAddr + 2 * k);
                ldsm_x4(bb[0], bb[1], bb[2], bb[3], bAddr + 2 * k);
                ldsm_x4(bb[4], bb[5], bb[6], bb[7], bAddr + bStep + 2 * k);
                mma16816(c[0], a, bb + 0);
                mma16816(c[1], a, bb + 2);
                mma16816(c[2], a, bb + 4);
                mma16816(c[3], a, bb + 6);
            }
            // per-warp partial column sums of relu(AZ + b2) -> pool2[warp][col]
            #pragma unroll
            for (int nt = 0; nt < 4; nt++) {
                int col = nt * 8 + 2 * tg;
                float bc0 = b2s[col], bc1 = b2s[col + 1];
                float s0 = fmaxf(c[nt][0] + bc0, 0.f) + fmaxf(c[nt][2] + bc0, 0.f);
                float s1 = fmaxf(c[nt][1] + bc1, 0.f) + fmaxf(c[nt][3] + bc1, 0.f);
                #pragma unroll
                for (int off = 16; off >= 4; off >>= 1) {
                    s0 += __shfl_down_sync(0xffffffffu, s0, off);
                    s1 += __shfl_down_sync(0xffffffffu, s1, off);
                }
                if (g == 0) {
                    pool2[warp * 32 + col]     = s0;
                    pool2[warp * 32 + col + 1] = s1;
                }
            }
        }
        __syncthreads();

        // ---------- MLP head on warp 0; warps 1-7 immediately loop to stage next A ----------
        if (warp == 0) {
            float h = 0.f;
            #pragma unroll
            for (int w = 0; w < 8; w++) h += pool2[w * 32 + lane];
            h *= (1.f / 128.f);
            float a3 = b3[lane];
            #pragma unroll
            for (int i = 0; i < 32; i++)
                a3 = fmaf(__shfl_sync(0xffffffffu, h, i), W3[i * 32 + lane], a3);
            a3 = fmaxf(a3, 0.f);
            int l16 = lane & 15;
            float a4 = b4[l16];
            #pragma unroll
            for (int i = 0; i < 32; i++)
                a4 = fmaf(__shfl_sync(0xffffffffu, a3, i), W4[i * 16 + l16], a4);
            a4 = fmaxf(a4, 0.f);
            float y = 0.f;
            #pragma unroll
            for (int i = 0; i < 16; i++)
                y = fmaf(__shfl_sync(0xffffffffu, a4, i), W5[i], y);
            if (lane == 0) out[gr] = y + b5[0];
        }
        // no barrier: staging is warp-local; all warps re-converge at the
        // post-stage __syncthreads() with identical barrier counts.
    }
}

extern "C" void kernel_launch(void* const* d_in, const int* in_sizes, int n_in,
                              void* d_out, int out_size)
{
    const float* X  = (const float*)d_in[0];
    const float* A  = (const float*)d_in[1];
    const float* W1 = (const float*)d_in[2];
    const float* b1 = (const float*)d_in[3];
    const float* W2 = (const float*)d_in[4];
    const float* b2 = (const float*)d_in[5];
    const float* W3 = (const float*)d_in[6];
    const float* b3 = (const float*)d_in[7];
    const float* W4 = (const float*)d_in[8];
    const float* b4 = (const float*)d_in[9];
    const float* W5 = (const float*)d_in[10];
    const float* b5 = (const float*)d_in[11];
    float* out = (float*)d_out;

    int batch = in_sizes[1] / (NA * NA);
    int grid  = 444;                       // 3 CTAs/SM * 148 SMs, persistent
    if (grid > batch) grid = batch;
    if (grid < 1) grid = 1;

    cudaFuncSetAttribute(gcn_fused_kernel,
                         cudaFuncAttributeMaxDynamicSharedMemorySize, SMEM_TOTAL);

    gcn_fused_kernel<<<grid, 256, SMEM_TOTAL>>>(X, A, W1, b1, W2, b2,
                                                W3, b3, W4, b4, W5, b5, out, batch);
}